// round 14
// baseline (speedup 1.0000x reference)
#include <cuda_runtime.h>
#include <cuda_bf16.h>
#include <math.h>
#include <stdint.h>

#define HID 128
#define DI 2048
#define DT 768
#define KTOT 2816
#define TSUP 1024
#define TQRY 16384
#define NTOK 17408
#define BK 64
#define NCH 44   /* 2816 / 64 */
#define STAGE 65536   /* per-stage: Ahi 16K, Alo 16K, Whi 16K, Wlo 16K */

// Scratch (static __device__ per allocation rules)
__device__ float g_C[NTOK * HID];     // LN1'd features (support blocks only)
__device__ float g_QF[TQRY * HID];
__device__ __nv_bfloat16 g_Whi[HID * KTOT];
__device__ __nv_bfloat16 g_Wlo[HID * KTOT];
__device__ __nv_bfloat16 g_Wvhi[HID * HID];
__device__ __nv_bfloat16 g_Wvlo[HID * HID];
__device__ __nv_bfloat16 g_Wohi[HID * HID];
__device__ __nv_bfloat16 g_Wolo[HID * HID];

// ---------------------------------------------------------------------------
// helpers
// ---------------------------------------------------------------------------
__device__ __forceinline__ uint32_t smem_u32_of(const void* p) {
    uint32_t a;
    asm("{ .reg .u64 t; cvta.to.shared.u64 t, %1; cvt.u32.u64 %0, t; }"
        : "=r"(a) : "l"(p));
    return a;
}
static __device__ __forceinline__ uint32_t sw128(uint32_t off) {
    return off ^ ((off >> 3) & 0x70);
}
__device__ __forceinline__ void ldsm4(uint32_t* r, uint32_t addr) {
    asm volatile("ldmatrix.sync.aligned.m8n8.x4.shared.b16 {%0,%1,%2,%3}, [%4];"
                 : "=r"(r[0]), "=r"(r[1]), "=r"(r[2]), "=r"(r[3]) : "r"(addr));
}
__device__ __forceinline__ void mma16816(float* c, const uint32_t* a, const uint32_t* b) {
    asm volatile(
        "mma.sync.aligned.m16n8k16.row.col.f32.bf16.bf16.f32 "
        "{%0,%1,%2,%3}, {%4,%5,%6,%7}, {%8,%9}, {%0,%1,%2,%3};"
        : "+f"(c[0]), "+f"(c[1]), "+f"(c[2]), "+f"(c[3])
        : "r"(a[0]), "r"(a[1]), "r"(a[2]), "r"(a[3]), "r"(b[0]), "r"(b[1]));
}
__device__ __forceinline__ void cp16(uint32_t dst, const void* src) {
    asm volatile("cp.async.cg.shared.global [%0], [%1], 16;"
                 :: "r"(dst), "l"(src) : "memory");
}
#define CP_COMMIT() asm volatile("cp.async.commit_group;" ::: "memory")
#define CP_WAIT0()  asm volatile("cp.async.wait_group 0;" ::: "memory")
#define CP_WAIT1()  asm volatile("cp.async.wait_group 1;" ::: "memory")

__device__ __forceinline__ void split2(float x, float y, uint32_t& hi, uint32_t& lo) {
    __nv_bfloat162 h = __float22bfloat162_rn(make_float2(x, y));
    float2 hf = __bfloat1622float2(h);
    __nv_bfloat162 l = __float22bfloat162_rn(make_float2(x - hf.x, y - hf.y));
    hi = *(uint32_t*)&h;
    lo = *(uint32_t*)&l;
}

// ---------------------------------------------------------------------------
// 16-warp fragment map + 32x32-tile bf16x3 compute over one 64-K chunk
// ---------------------------------------------------------------------------
struct Frag16 {
    uint32_t abase[2], aswz[2], bbase[2], bswz[2];
};
__device__ __forceinline__ void make_frag16(Frag16& fm, int lane, int mw, int nw) {
    #pragma unroll
    for (int mt = 0; mt < 2; ++mt) {
        uint32_t rb = (uint32_t)(mw * 32 + mt * 16 + (lane & 15)) * 128 + (lane >> 4) * 16;
        fm.abase[mt] = rb; fm.aswz[mt] = (rb >> 3) & 0x70;
    }
    #pragma unroll
    for (int p = 0; p < 2; ++p) {
        uint32_t rb = (uint32_t)(nw * 32 + p * 16 + ((lane >> 4) & 1) * 8 + (lane & 7)) * 128
                    + ((lane >> 3) & 1) * 16;
        fm.bbase[p] = rb; fm.bswz[p] = (rb >> 3) & 0x70;
    }
}
__device__ __forceinline__ void compute_c16(
    uint32_t AHI, uint32_t ALO, uint32_t WHI, uint32_t WLO,
    const Frag16& fm, float (*acc)[4][4])
{
    #pragma unroll
    for (int ks = 0; ks < 4; ++ks) {
        uint32_t ahi[2][4], alo[2][4];
        #pragma unroll
        for (int mt = 0; mt < 2; ++mt) {
            uint32_t o = (fm.abase[mt] + ks * 32) ^ fm.aswz[mt];
            ldsm4(ahi[mt], AHI + o);
            ldsm4(alo[mt], ALO + o);
        }
        uint32_t bhi[2][4], blo[2][4];
        #pragma unroll
        for (int p = 0; p < 2; ++p) {
            uint32_t o = (fm.bbase[p] + ks * 32) ^ fm.bswz[p];
            ldsm4(bhi[p], WHI + o);
            ldsm4(blo[p], WLO + o);
        }
        #pragma unroll
        for (int mt = 0; mt < 2; ++mt)
            #pragma unroll
            for (int j = 0; j < 4; ++j)
                mma16816(acc[mt][j], ahi[mt], &bhi[j >> 1][(j & 1) * 2]);
        #pragma unroll
        for (int mt = 0; mt < 2; ++mt)
            #pragma unroll
            for (int j = 0; j < 4; ++j)
                mma16816(acc[mt][j], ahi[mt], &blo[j >> 1][(j & 1) * 2]);
        #pragma unroll
        for (int mt = 0; mt < 2; ++mt)
            #pragma unroll
            for (int j = 0; j < 4; ++j)
                mma16816(acc[mt][j], alo[mt], &bhi[j >> 1][(j & 1) * 2]);
    }
}

// ---------------------------------------------------------------------------
// Single weight-preconvert kernel: blocks [0,352) main W, [352,368) Wv,
// [368,384) Wo.
// ---------------------------------------------------------------------------
__global__ void __launch_bounds__(256) k_wconv_all(
    const float* __restrict__ Wi, const float* __restrict__ Wt,
    const float* __restrict__ Wv, const float* __restrict__ Wo)
{
    int b = blockIdx.x;
    if (b < 352) {
        int f4 = b * 256 + threadIdx.x;
        if (f4 >= HID * KTOT / 4) return;
        int row = f4 / (KTOT / 4);
        int col = (f4 % (KTOT / 4)) * 4;
        float4 v;
        if (col < DI) v = *(const float4*)(Wi + (size_t)row * DI + col);
        else          v = *(const float4*)(Wt + (size_t)row * DT + (col - DI));
        uint2 uh, ul;
        split2(v.x, v.y, uh.x, ul.x);
        split2(v.z, v.w, uh.y, ul.y);
        *(uint2*)(g_Whi + (size_t)row * KTOT + col) = uh;
        *(uint2*)(g_Wlo + (size_t)row * KTOT + col) = ul;
    } else {
        const bool isV = (b < 368);
        int f4 = (b - (isV ? 352 : 368)) * 256 + threadIdx.x;
        const float* W = isV ? Wv : Wo;
        __nv_bfloat16* hi = isV ? g_Wvhi : g_Wohi;
        __nv_bfloat16* lo = isV ? g_Wvlo : g_Wolo;
        float4 v = *(const float4*)(W + (size_t)f4 * 4);
        uint2 uh, ul;
        split2(v.x, v.y, uh.x, ul.x);
        split2(v.z, v.w, uh.y, ul.y);
        *(uint2*)(hi + (size_t)f4 * 4) = uh;
        *(uint2*)(lo + (size_t)f4 * 4) = ul;
    }
}

// ---------------------------------------------------------------------------
// MEGA KERNEL (unchanged): input projection + LN1; query blocks continue
// through LN2/Wv/Wo to g_QF, support blocks write g_C.
// ---------------------------------------------------------------------------
__global__ void __launch_bounds__(512) k_input_mega(
    const float* __restrict__ s_img, const float* __restrict__ s_txt,
    const float* __restrict__ q_img, const float* __restrict__ q_txt,
    const float* __restrict__ bi, const float* __restrict__ bt,
    const float* __restrict__ g1, const float* __restrict__ b1,
    const float* __restrict__ bv, const float* __restrict__ g2,
    const float* __restrict__ b2, const float* __restrict__ bo)
{
    extern __shared__ char smem[];
    const uint32_t sb = smem_u32_of(smem);
    float* bsum = (float*)smem;
    const uint32_t BASE = sb + 2048;

    const int tid = threadIdx.x, lane = tid & 31, wid = tid >> 5;
    const int mw = wid & 3, nw = wid >> 2;
    const int tokbase = blockIdx.x * 128;
    const bool isQuery = (tokbase >= TSUP);

    const float* img; const float* txt;
    if (!isQuery) {
        img = s_img + (size_t)tokbase * DI;
        txt = s_txt + (size_t)tokbase * DT;
    } else {
        img = q_img + (size_t)(tokbase - TSUP) * DI;
        txt = q_txt + (size_t)(tokbase - TSUP) * DT;
    }
    if (tid < HID) bsum[tid] = bi[tid] + bt[tid];

    const int row = tid >> 2;
    const int cq  = (tid & 3) * 16;

    Frag16 fm;
    make_frag16(fm, lane, mw, nw);

    float acc[2][4][4];
    #pragma unroll
    for (int mt = 0; mt < 2; ++mt)
        #pragma unroll
        for (int j = 0; j < 4; ++j)
            #pragma unroll
            for (int q = 0; q < 4; ++q) acc[mt][j][q] = 0.0f;

    float4 areg[4];
    auto loadA = [&](int c) {
        int kg = c * BK;
        const float4* ap;
        if (kg < DI) ap = (const float4*)(img + (size_t)row * DI + kg + cq);
        else         ap = (const float4*)(txt + (size_t)row * DT + (kg - DI) + cq);
        #pragma unroll
        for (int i = 0; i < 4; ++i) areg[i] = ap[i];
    };
    auto storeA = [&](uint32_t buf) {
        char* pAhi = smem + (buf - sb);
        char* pAlo = pAhi + 16384;
        #pragma unroll
        for (int i = 0; i < 4; ++i) {
            float4 f = areg[i];
            uint2 uh, ul;
            split2(f.x, f.y, uh.x, ul.x);
            split2(f.z, f.w, uh.y, ul.y);
            uint32_t off = sw128((uint32_t)(row * 128 + (cq + i * 4) * 2));
            *(uint2*)(pAhi + off) = uh;
            *(uint2*)(pAlo + off) = ul;
        }
    };
    auto loadW = [&](int c, uint32_t buf) {
        int kg = c * BK;
        const __nv_bfloat16* sh = g_Whi + (size_t)row * KTOT + kg + cq;
        const __nv_bfloat16* sl = g_Wlo + (size_t)row * KTOT + kg + cq;
        #pragma unroll
        for (int i = 0; i < 2; ++i) {
            uint32_t off = sw128((uint32_t)(row * 128 + (cq + i * 8) * 2));
            cp16(buf + 32768 + off, sh + i * 8);
            cp16(buf + 49152 + off, sl + i * 8);
        }
    };

    loadA(0); storeA(BASE + 0 * STAGE); loadW(0, BASE + 0 * STAGE); CP_COMMIT();
    loadA(1); storeA(BASE + 1 * STAGE); loadW(1, BASE + 1 * STAGE); CP_COMMIT();
    loadA(2);

    for (int c = 0; c < NCH; ++c) {
        if (c + 1 < NCH) CP_WAIT1(); else CP_WAIT0();
        __syncthreads();
        if (c + 2 < NCH) {
            uint32_t nbuf = BASE + (uint32_t)((c + 2) % 3) * STAGE;
            storeA(nbuf);
            loadW(c + 2, nbuf);
            CP_COMMIT();
            if (c + 3 < NCH) loadA(c + 3);
        }
        uint32_t cur = BASE + (uint32_t)(c % 3) * STAGE;
        compute_c16(cur, cur + 16384, cur + 32768, cur + 49152, fm, acc);
    }

    __syncthreads();
    float* Vs = (float*)(smem + 2048);
    const uint32_t CN = BASE + 1 * STAGE;
    const uint32_t WT = BASE + 2 * STAGE;

    const int schunk = (tid >> 1) & 1;
    const int sch = (tid & 1) * 32;
    auto loadWpair = [&](const __nv_bfloat16* hi, const __nv_bfloat16* lo, uint32_t dst) {
        const __nv_bfloat16* h = hi + (size_t)row * HID + schunk * BK + sch;
        const __nv_bfloat16* l = lo + (size_t)row * HID + schunk * BK + sch;
        #pragma unroll
        for (int i = 0; i < 4; ++i) {
            uint32_t off = sw128((uint32_t)(row * 128 + (sch + i * 8) * 2));
            cp16(dst + schunk * 32768 + off, h + i * 8);
            cp16(dst + schunk * 32768 + 16384 + off, l + i * 8);
        }
    };
    if (isQuery) { loadWpair(g_Wvhi, g_Wvlo, WT); CP_COMMIT(); }

    {
        const int g = lane >> 2, t = lane & 3;
        #pragma unroll
        for (int mt = 0; mt < 2; ++mt) {
            int r0 = mw * 32 + mt * 16 + g;
            #pragma unroll
            for (int j = 0; j < 4; ++j) {
                int col = nw * 32 + j * 8 + t * 2;
                float b0 = bsum[col], b1v = bsum[col + 1];
                *(float2*)&Vs[r0 * 128 + col] =
                    make_float2(acc[mt][j][0] + b0, acc[mt][j][1] + b1v);
                *(float2*)&Vs[(r0 + 8) * 128 + col] =
                    make_float2(acc[mt][j][2] + b0, acc[mt][j][3] + b1v);
            }
        }
    }
    __syncthreads();

    const int cch = lane >> 4;
    const int lc  = (lane * 4) & 63;
    {
        float4 gg = ((const float4*)g1)[lane];
        float4 bb = ((const float4*)b1)[lane];
        char* pNhi = smem + 2048 + STAGE + cch * 32768;
        char* pNlo = pNhi + 16384;
        for (int tt = wid * 8; tt < wid * 8 + 8; ++tt) {
            float4 x = ((const float4*)&Vs[tt * 128])[lane];
            float s = x.x + x.y + x.z + x.w;
            #pragma unroll
            for (int o = 16; o > 0; o >>= 1) s += __shfl_xor_sync(0xffffffffu, s, o);
            float mean = s * (1.0f / 128.0f);
            float d0 = x.x - mean, d1 = x.y - mean, d2 = x.z - mean, d3 = x.w - mean;
            float v = d0*d0 + d1*d1 + d2*d2 + d3*d3;
            #pragma unroll
            for (int o = 16; o > 0; o >>= 1) v += __shfl_xor_sync(0xffffffffu, v, o);
            float inv = rsqrtf(v * (1.0f / 128.0f) + 1e-5f);
            float y0 = d0 * inv * gg.x + bb.x;
            float y1 = d1 * inv * gg.y + bb.y;
            float y2 = d2 * inv * gg.z + bb.z;
            float y3 = d3 * inv * gg.w + bb.w;
            if (!isQuery) {
                float4 y = make_float4(y0, y1, y2, y3);
                ((float4*)&g_C[(size_t)(tokbase + tt) * HID])[lane] = y;
            } else {
                uint2 uh, ul;
                split2(y0, y1, uh.x, ul.x);
                split2(y2, y3, uh.y, ul.y);
                uint32_t off = sw128((uint32_t)(tt * 128 + lc * 2));
                *(uint2*)(pNhi + off) = uh;
                *(uint2*)(pNlo + off) = ul;
            }
        }
    }
    if (!isQuery) return;

    CP_WAIT0();
    __syncthreads();

    #pragma unroll
    for (int mt = 0; mt < 2; ++mt)
        #pragma unroll
        for (int j = 0; j < 4; ++j)
            #pragma unroll
            for (int q = 0; q < 4; ++q) acc[mt][j][q] = 0.0f;
    #pragma unroll
    for (int c = 0; c < 2; ++c)
        compute_c16(CN + c * 32768, CN + c * 32768 + 16384,
                    WT + c * 32768, WT + c * 32768 + 16384, fm, acc);
    __syncthreads();

    loadWpair(g_Wohi, g_Wolo, CN);
    CP_COMMIT();

    {
        const int g = lane >> 2, t = lane & 3;
        #pragma unroll
        for (int mt = 0; mt < 2; ++mt) {
            int r0 = mw * 32 + mt * 16 + g;
            #pragma unroll
            for (int j = 0; j < 4; ++j) {
                int col = nw * 32 + j * 8 + t * 2;
                float b0 = bv[col], b1v = bv[col + 1];
                *(float2*)&Vs[r0 * 128 + col] =
                    make_float2(acc[mt][j][0] + b0, acc[mt][j][1] + b1v);
                *(float2*)&Vs[(r0 + 8) * 128 + col] =
                    make_float2(acc[mt][j][2] + b0, acc[mt][j][3] + b1v);
            }
        }
    }
    __syncthreads();

    {
        float4 gg = ((const float4*)g2)[lane];
        float4 bb = ((const float4*)b2)[lane];
        char* pNhi = smem + 2048 + 2 * STAGE + cch * 32768;
        char* pNlo = pNhi + 16384;
        for (int tt = wid * 8; tt < wid * 8 + 8; ++tt) {
            float4 x = ((const float4*)&Vs[tt * 128])[lane];
            float s = x.x + x.y + x.z + x.w;
            #pragma unroll
            for (int o = 16; o > 0; o >>= 1) s += __shfl_xor_sync(0xffffffffu, s, o);
            float mean = s * (1.0f / 128.0f);
            float d0 = x.x - mean, d1 = x.y - mean, d2 = x.z - mean, d3 = x.w - mean;
            float v = d0*d0 + d1*d1 + d2*d2 + d3*d3;
            #pragma unroll
            for (int o = 16; o > 0; o >>= 1) v += __shfl_xor_sync(0xffffffffu, v, o);
            float inv = rsqrtf(v * (1.0f / 128.0f) + 1e-5f);
            float y0 = d0 * inv * gg.x + bb.x;
            float y1 = d1 * inv * gg.y + bb.y;
            float y2 = d2 * inv * gg.z + bb.z;
            float y3 = d3 * inv * gg.w + bb.w;
            uint2 uh, ul;
            split2(y0, y1, uh.x, ul.x);
            split2(y2, y3, uh.y, ul.y);
            uint32_t off = sw128((uint32_t)(tt * 128 + lc * 2));
            *(uint2*)(pNhi + off) = uh;
            *(uint2*)(pNlo + off) = ul;
        }
    }
    CP_WAIT0();
    __syncthreads();

    #pragma unroll
    for (int mt = 0; mt < 2; ++mt)
        #pragma unroll
        for (int j = 0; j < 4; ++j)
            #pragma unroll
            for (int q = 0; q < 4; ++q) acc[mt][j][q] = 0.0f;
    #pragma unroll
    for (int c = 0; c < 2; ++c)
        compute_c16(WT + c * 32768, WT + c * 32768 + 16384,
                    CN + c * 32768, CN + c * 32768 + 16384, fm, acc);

    {
        const int g = lane >> 2, t = lane & 3;
        const int qbase = tokbase - TSUP;
        #pragma unroll
        for (int mt = 0; mt < 2; ++mt) {
            int r0 = qbase + mw * 32 + mt * 16 + g;
            #pragma unroll
            for (int j = 0; j < 4; ++j) {
                int col = nw * 32 + j * 8 + t * 2;
                float b0 = bo[col], b1v = bo[col + 1];
                *(float2*)&g_QF[(size_t)r0 * HID + col] =
                    make_float2(acc[mt][j][0] + b0, acc[mt][j][1] + b1v);
                *(float2*)&g_QF[(size_t)(r0 + 8) * HID + col] =
                    make_float2(acc[mt][j][2] + b0, acc[mt][j][3] + b1v);
            }
        }
    }
}

// ---------------------------------------------------------------------------
// Fused tail v2: per task t — support attention + cosine logits.
// Weight matrices are staged into smem COALESCED (stride-132 rows) and the
// GEMVs read them via conflict-free LDS.128 — fixes the 32x L1-wavefront
// amplification of the per-thread strided LDG pattern.
// ---------------------------------------------------------------------------
#define WSTR 132
__global__ void __launch_bounds__(128) k_tail(
    const float* __restrict__ C,
    const float* __restrict__ Wq, const float* __restrict__ bq,
    const float* __restrict__ Wk, const float* __restrict__ bk,
    const float* __restrict__ Wv, const float* __restrict__ bv,
    const float* __restrict__ g2, const float* __restrict__ b2,
    const float* __restrict__ Wo, const float* __restrict__ bo,
    const float* __restrict__ QF, float* __restrict__ out)
{
    extern __shared__ float sW[];          // [128][WSTR] staged weight matrix
    __shared__ float cs[4][HID], qs[4][HID], ks_[4][HID], vs[4][HID];
    __shared__ float am[4][4];
    __shared__ float cx[4][HID];
    __shared__ float pn[4][HID];
    int t = blockIdx.x;
    int j = threadIdx.x;
    const float* base = C + (size_t)t * 4 * HID;
    #pragma unroll
    for (int s = 0; s < 4; ++s) cs[s][j] = base[s * HID + j];

    auto stageW = [&](const float* W) {
        const float4* W4 = (const float4*)W;
        #pragma unroll 8
        for (int k = 0; k < 32; ++k) {
            int idx = k * 128 + j;          // coalesced across threads
            int r = idx >> 5, c4 = idx & 31;
            float4 v = W4[idx];
            *(float4*)&sW[r * WSTR + c4 * 4] = v;
        }
    };
    // GEMV from staged sW: row j dot cs[s][:], for 4 tokens
    auto gemv = [&](float* a) {
        a[0] = a[1] = a[2] = a[3] = 0.0f;
        #pragma unroll 8
        for (int d4 = 0; d4 < 32; ++d4) {
            float4 w4 = *(const float4*)&sW[j * WSTR + d4 * 4];
            #pragma unroll
            for (int s = 0; s < 4; ++s) {
                a[s] += w4.x * cs[s][d4*4+0] + w4.y * cs[s][d4*4+1]
                      + w4.z * cs[s][d4*4+2] + w4.w * cs[s][d4*4+3];
            }
        }
    };

    float a[4];
    stageW(Wq); __syncthreads();
    gemv(a);
    #pragma unroll
    for (int s = 0; s < 4; ++s) qs[s][j] = a[s] + bq[j];
    __syncthreads();
    stageW(Wk); __syncthreads();
    gemv(a);
    #pragma unroll
    for (int s = 0; s < 4; ++s) ks_[s][j] = a[s] + bk[j];
    __syncthreads();
    stageW(Wv); __syncthreads();
    gemv(a);
    #pragma unroll
    for (int s = 0; s < 4; ++s) vs[s][j] = a[s] + bv[j];
    __syncthreads();

    if (j < 16) {
        int s = j >> 2, s2 = j & 3;
        float d = 0.0f;
        for (int dd = 0; dd < HID; ++dd) d += qs[s][dd] * ks_[s2][dd];
        am[s][s2] = d * (1.0f / (sqrtf(128.0f) + 1e-8f));
    }
    __syncthreads();
    if (j < 4) {
        float r[4];
        float mx = -1e30f;
        #pragma unroll
        for (int c = 0; c < 4; ++c) { r[c] = am[j][c]; mx = fmaxf(mx, r[c]); }
        float sum = 0.0f;
        #pragma unroll
        for (int c = 0; c < 4; ++c) { r[c] = expf(r[c] - mx); sum += r[c]; }
        #pragma unroll
        for (int c = 0; c < 4; ++c) r[c] /= sum;
        float sum2 = 0.0f;
        #pragma unroll
        for (int c = 0; c < 4; ++c) { r[c] += 1e-10f; sum2 += r[c]; }
        #pragma unroll
        for (int c = 0; c < 4; ++c) {
            r[c] /= sum2;
            am[j][c] = fminf(fmaxf(r[c], 1e-7f), 1.0f);
        }
    }
    __syncthreads();
    #pragma unroll
    for (int s = 0; s < 4; ++s) {
        float v = 0.0f;
        #pragma unroll
        for (int s2 = 0; s2 < 4; ++s2) v += am[s][s2] * vs[s2][j];
        cx[s][j] = v;
    }
    __syncthreads();
    {
        int w = j >> 5, lane = j & 31;
        float x0 = cx[w][lane], x1 = cx[w][lane+32], x2 = cx[w][lane+64], x3 = cx[w][lane+96];
        float s = x0 + x1 + x2 + x3;
        #pragma unroll
        for (int o = 16; o > 0; o >>= 1) s += __shfl_xor_sync(0xffffffffu, s, o);
        float mean = s * (1.0f / 128.0f);
        float d0 = x0 - mean, d1 = x1 - mean, d2 = x2 - mean, d3 = x3 - mean;
        float v = d0*d0 + d1*d1 + d2*d2 + d3*d3;
        #pragma unroll
        for (int o = 16; o > 0; o >>= 1) v += __shfl_xor_sync(0xffffffffu, v, o);
        float inv = rsqrtf(v * (1.0f / 128.0f) + 1e-5f);
        cx[w][lane]    = d0 * inv * g2[lane]    + b2[lane];
        cx[w][lane+32] = d1 * inv * g2[lane+32] + b2[lane+32];
        cx[w][lane+64] = d2 * inv * g2[lane+64] + b2[lane+64];
        cx[w][lane+96] = d3 * inv * g2[lane+96] + b2[lane+96];
    }
    __syncthreads();
    stageW(Wo); __syncthreads();
    {
        float ao[4] = {0,0,0,0};
        #pragma unroll 8
        for (int d4 = 0; d4 < 32; ++d4) {
            float4 w4 = *(const float4*)&sW[j * WSTR + d4 * 4];
            #pragma unroll
            for (int s = 0; s < 4; ++s) {
                ao[s] += w4.x * cx[s][d4*4+0] + w4.y * cx[s][d4*4+1]
                       + w4.z * cx[s][d4*4+2] + w4.w * cx[s][d4*4+3];
            }
        }
        #pragma unroll
        for (int s = 0; s < 4; ++s)
            qs[s][j] = ao[s] + bo[j];      // SF rows (reuse qs)
    }
    __syncthreads();

    // normalize SF rows -> pn
    int w = j >> 5, lane = j & 31;
    {
        float4 x = ((const float4*)qs[w])[lane];
        float n2 = x.x*x.x + x.y*x.y + x.z*x.z + x.w*x.w;
        #pragma unroll
        for (int o = 16; o > 0; o >>= 1) n2 += __shfl_xor_sync(0xffffffffu, n2, o);
        float inv = 1.0f / fmaxf(sqrtf(n2), 1e-8f);
        float4 y;
        y.x = x.x * inv; y.y = x.y * inv; y.z = x.z * inv; y.w = x.w * inv;
        ((float4*)pn[w])[lane] = y;
    }
    __syncthreads();

    // cosine logits against this task's 64 QF rows
    for (int q = w; q < 64; q += 4) {
        const float4* row = (const float4*)(QF + (size_t)(t*64 + q) * HID);
        float4 x = row[lane];
        float n2 = x.x*x.x + x.y*x.y + x.z*x.z + x.w*x.w;
        float d[4];
        #pragma unroll
        for (int c = 0; c < 4; ++c) {
            float4 p = ((const float4*)pn[c])[lane];
            d[c] = x.x*p.x + x.y*p.y + x.z*p.z + x.w*p.w;
        }
        #pragma unroll
        for (int o = 16; o > 0; o >>= 1) {
            n2 += __shfl_xor_sync(0xffffffffu, n2, o);
            #pragma unroll
            for (int c = 0; c < 4; ++c)
                d[c] += __shfl_xor_sync(0xffffffffu, d[c], o);
        }
        if (lane == 0) {
            float inv = 10.0f / fmaxf(sqrtf(n2), 1e-8f);
            float4 r;
            r.x = d[0]*inv; r.y = d[1]*inv; r.z = d[2]*inv; r.w = d[3]*inv;
            ((float4*)(out + ((size_t)t*64 + q) * 4))[0] = r;
        }
    }
}

extern "C" void kernel_launch(void* const* d_in, const int* in_sizes, int n_in,
                              void* d_out, int out_size)
{
    const float* s_img = (const float*)d_in[0];
    const float* s_txt = (const float*)d_in[1];
    /* d_in[2] = support_labels (unused) */
    const float* q_img = (const float*)d_in[3];
    const float* q_txt = (const float*)d_in[4];
    const float* Wi = (const float*)d_in[5];
    const float* bi = (const float*)d_in[6];
    const float* Wt = (const float*)d_in[7];
    const float* bt = (const float*)d_in[8];
    const float* g1 = (const float*)d_in[9];
    const float* b1 = (const float*)d_in[10];
    const float* Wq = (const float*)d_in[11];
    const float* bq = (const float*)d_in[12];
    const float* Wk = (const float*)d_in[13];
    const float* bk = (const float*)d_in[14];
    const float* Wv = (const float*)d_in[15];
    const float* bv = (const float*)d_in[16];
    const float* g2 = (const float*)d_in[17];
    const float* b2 = (const float*)d_in[18];
    const float* Wo = (const float*)d_in[19];
    const float* bo = (const float*)d_in[20];

    float *pC, *pQF;
    cudaGetSymbolAddress((void**)&pC, g_C);
    cudaGetSymbolAddress((void**)&pQF, g_QF);

    const int SMEM_IN = 2048 + 3 * STAGE;        // 198656
    const int SMEM_TAIL = 128 * WSTR * 4;        // 67584
    static bool attr_set = false;
    if (!attr_set) {
        cudaFuncSetAttribute(k_input_mega,
                             cudaFuncAttributeMaxDynamicSharedMemorySize, SMEM_IN);
        cudaFuncSetAttribute(k_tail,
                             cudaFuncAttributeMaxDynamicSharedMemorySize, SMEM_TAIL);
        attr_set = true;
    }

    // 1) single weight-preconvert launch
    k_wconv_all<<<384, 256>>>(Wi, Wt, Wv, Wo);
    // 2) mega kernel: input projection + LN1 (+ full query chain for query blocks)
    k_input_mega<<<NTOK / 128, 512, SMEM_IN>>>(s_img, s_txt, q_img, q_txt,
                                               bi, bt, g1, b1, bv, g2, b2, bo);
    // 3) fused tail: support attention + cosine logits, one block per task
    k_tail<<<256, 128, SMEM_TAIL>>>(pC, Wq, bq, Wk, bk, Wv, bv, g2, b2, Wo, bo,
                                    pQF, (float*)d_out);
}

// round 15
// speedup vs baseline: 1.5434x; 1.5434x over previous
#include <cuda_runtime.h>
#include <cuda_bf16.h>
#include <math.h>
#include <stdint.h>

#define HID 128
#define DI 2048
#define DT 768
#define KTOT 2816
#define TSUP 1024
#define TQRY 16384
#define NTOK 17408
#define BK 64
#define NCH 44   /* 2816 / 64 */
#define STAGE 65536   /* per-stage: Ahi 16K, Alo 16K, Whi 16K, Wlo 16K */

// Scratch (static __device__ per allocation rules)
__device__ float g_C[NTOK * HID];     // LN1'd features (support blocks only)
__device__ float g_QF[TQRY * HID];
__device__ __nv_bfloat16 g_Whi[HID * KTOT];
__device__ __nv_bfloat16 g_Wlo[HID * KTOT];
__device__ __nv_bfloat16 g_Wvhi[HID * HID];
__device__ __nv_bfloat16 g_Wvlo[HID * HID];
__device__ __nv_bfloat16 g_Wohi[HID * HID];
__device__ __nv_bfloat16 g_Wolo[HID * HID];

// ---------------------------------------------------------------------------
// helpers
// ---------------------------------------------------------------------------
__device__ __forceinline__ uint32_t smem_u32_of(const void* p) {
    uint32_t a;
    asm("{ .reg .u64 t; cvta.to.shared.u64 t, %1; cvt.u32.u64 %0, t; }"
        : "=r"(a) : "l"(p));
    return a;
}
static __device__ __forceinline__ uint32_t sw128(uint32_t off) {
    return off ^ ((off >> 3) & 0x70);
}
__device__ __forceinline__ void ldsm4(uint32_t* r, uint32_t addr) {
    asm volatile("ldmatrix.sync.aligned.m8n8.x4.shared.b16 {%0,%1,%2,%3}, [%4];"
                 : "=r"(r[0]), "=r"(r[1]), "=r"(r[2]), "=r"(r[3]) : "r"(addr));
}
__device__ __forceinline__ void mma16816(float* c, const uint32_t* a, const uint32_t* b) {
    asm volatile(
        "mma.sync.aligned.m16n8k16.row.col.f32.bf16.bf16.f32 "
        "{%0,%1,%2,%3}, {%4,%5,%6,%7}, {%8,%9}, {%0,%1,%2,%3};"
        : "+f"(c[0]), "+f"(c[1]), "+f"(c[2]), "+f"(c[3])
        : "r"(a[0]), "r"(a[1]), "r"(a[2]), "r"(a[3]), "r"(b[0]), "r"(b[1]));
}
__device__ __forceinline__ void cp16(uint32_t dst, const void* src) {
    asm volatile("cp.async.cg.shared.global [%0], [%1], 16;"
                 :: "r"(dst), "l"(src) : "memory");
}
#define CP_COMMIT() asm volatile("cp.async.commit_group;" ::: "memory")
#define CP_WAIT0()  asm volatile("cp.async.wait_group 0;" ::: "memory")
#define CP_WAIT1()  asm volatile("cp.async.wait_group 1;" ::: "memory")

__device__ __forceinline__ void split2(float x, float y, uint32_t& hi, uint32_t& lo) {
    __nv_bfloat162 h = __float22bfloat162_rn(make_float2(x, y));
    float2 hf = __bfloat1622float2(h);
    __nv_bfloat162 l = __float22bfloat162_rn(make_float2(x - hf.x, y - hf.y));
    hi = *(uint32_t*)&h;
    lo = *(uint32_t*)&l;
}

// ---------------------------------------------------------------------------
// 16-warp fragment map + 32x32-tile bf16x3 compute over one 64-K chunk
// ---------------------------------------------------------------------------
struct Frag16 {
    uint32_t abase[2], aswz[2], bbase[2], bswz[2];
};
__device__ __forceinline__ void make_frag16(Frag16& fm, int lane, int mw, int nw) {
    #pragma unroll
    for (int mt = 0; mt < 2; ++mt) {
        uint32_t rb = (uint32_t)(mw * 32 + mt * 16 + (lane & 15)) * 128 + (lane >> 4) * 16;
        fm.abase[mt] = rb; fm.aswz[mt] = (rb >> 3) & 0x70;
    }
    #pragma unroll
    for (int p = 0; p < 2; ++p) {
        uint32_t rb = (uint32_t)(nw * 32 + p * 16 + ((lane >> 4) & 1) * 8 + (lane & 7)) * 128
                    + ((lane >> 3) & 1) * 16;
        fm.bbase[p] = rb; fm.bswz[p] = (rb >> 3) & 0x70;
    }
}
__device__ __forceinline__ void compute_c16(
    uint32_t AHI, uint32_t ALO, uint32_t WHI, uint32_t WLO,
    const Frag16& fm, float (*acc)[4][4])
{
    #pragma unroll
    for (int ks = 0; ks < 4; ++ks) {
        uint32_t ahi[2][4], alo[2][4];
        #pragma unroll
        for (int mt = 0; mt < 2; ++mt) {
            uint32_t o = (fm.abase[mt] + ks * 32) ^ fm.aswz[mt];
            ldsm4(ahi[mt], AHI + o);
            ldsm4(alo[mt], ALO + o);
        }
        uint32_t bhi[2][4], blo[2][4];
        #pragma unroll
        for (int p = 0; p < 2; ++p) {
            uint32_t o = (fm.bbase[p] + ks * 32) ^ fm.bswz[p];
            ldsm4(bhi[p], WHI + o);
            ldsm4(blo[p], WLO + o);
        }
        #pragma unroll
        for (int mt = 0; mt < 2; ++mt)
            #pragma unroll
            for (int j = 0; j < 4; ++j)
                mma16816(acc[mt][j], ahi[mt], &bhi[j >> 1][(j & 1) * 2]);
        #pragma unroll
        for (int mt = 0; mt < 2; ++mt)
            #pragma unroll
            for (int j = 0; j < 4; ++j)
                mma16816(acc[mt][j], ahi[mt], &blo[j >> 1][(j & 1) * 2]);
        #pragma unroll
        for (int mt = 0; mt < 2; ++mt)
            #pragma unroll
            for (int j = 0; j < 4; ++j)
                mma16816(acc[mt][j], alo[mt], &bhi[j >> 1][(j & 1) * 2]);
    }
}

// ---------------------------------------------------------------------------
// Single weight-preconvert kernel: blocks [0,352) main W, [352,368) Wv,
// [368,384) Wo.
// ---------------------------------------------------------------------------
__global__ void __launch_bounds__(256) k_wconv_all(
    const float* __restrict__ Wi, const float* __restrict__ Wt,
    const float* __restrict__ Wv, const float* __restrict__ Wo)
{
    int b = blockIdx.x;
    if (b < 352) {
        int f4 = b * 256 + threadIdx.x;
        if (f4 >= HID * KTOT / 4) return;
        int row = f4 / (KTOT / 4);
        int col = (f4 % (KTOT / 4)) * 4;
        float4 v;
        if (col < DI) v = *(const float4*)(Wi + (size_t)row * DI + col);
        else          v = *(const float4*)(Wt + (size_t)row * DT + (col - DI));
        uint2 uh, ul;
        split2(v.x, v.y, uh.x, ul.x);
        split2(v.z, v.w, uh.y, ul.y);
        *(uint2*)(g_Whi + (size_t)row * KTOT + col) = uh;
        *(uint2*)(g_Wlo + (size_t)row * KTOT + col) = ul;
    } else {
        const bool isV = (b < 368);
        int f4 = (b - (isV ? 352 : 368)) * 256 + threadIdx.x;
        const float* W = isV ? Wv : Wo;
        __nv_bfloat16* hi = isV ? g_Wvhi : g_Wohi;
        __nv_bfloat16* lo = isV ? g_Wvlo : g_Wolo;
        float4 v = *(const float4*)(W + (size_t)f4 * 4);
        uint2 uh, ul;
        split2(v.x, v.y, uh.x, ul.x);
        split2(v.z, v.w, uh.y, ul.y);
        *(uint2*)(hi + (size_t)f4 * 4) = uh;
        *(uint2*)(lo + (size_t)f4 * 4) = ul;
    }
}

// ---------------------------------------------------------------------------
// MEGA KERNEL (unchanged): input projection + LN1; query blocks continue
// through LN2/Wv/Wo to g_QF, support blocks write g_C.
// ---------------------------------------------------------------------------
__global__ void __launch_bounds__(512) k_input_mega(
    const float* __restrict__ s_img, const float* __restrict__ s_txt,
    const float* __restrict__ q_img, const float* __restrict__ q_txt,
    const float* __restrict__ bi, const float* __restrict__ bt,
    const float* __restrict__ g1, const float* __restrict__ b1,
    const float* __restrict__ bv, const float* __restrict__ g2,
    const float* __restrict__ b2, const float* __restrict__ bo)
{
    extern __shared__ char smem[];
    const uint32_t sb = smem_u32_of(smem);
    float* bsum = (float*)smem;
    const uint32_t BASE = sb + 2048;

    const int tid = threadIdx.x, lane = tid & 31, wid = tid >> 5;
    const int mw = wid & 3, nw = wid >> 2;
    const int tokbase = blockIdx.x * 128;
    const bool isQuery = (tokbase >= TSUP);

    const float* img; const float* txt;
    if (!isQuery) {
        img = s_img + (size_t)tokbase * DI;
        txt = s_txt + (size_t)tokbase * DT;
    } else {
        img = q_img + (size_t)(tokbase - TSUP) * DI;
        txt = q_txt + (size_t)(tokbase - TSUP) * DT;
    }
    if (tid < HID) bsum[tid] = bi[tid] + bt[tid];

    const int row = tid >> 2;
    const int cq  = (tid & 3) * 16;

    Frag16 fm;
    make_frag16(fm, lane, mw, nw);

    float acc[2][4][4];
    #pragma unroll
    for (int mt = 0; mt < 2; ++mt)
        #pragma unroll
        for (int j = 0; j < 4; ++j)
            #pragma unroll
            for (int q = 0; q < 4; ++q) acc[mt][j][q] = 0.0f;

    float4 areg[4];
    auto loadA = [&](int c) {
        int kg = c * BK;
        const float4* ap;
        if (kg < DI) ap = (const float4*)(img + (size_t)row * DI + kg + cq);
        else         ap = (const float4*)(txt + (size_t)row * DT + (kg - DI) + cq);
        #pragma unroll
        for (int i = 0; i < 4; ++i) areg[i] = ap[i];
    };
    auto storeA = [&](uint32_t buf) {
        char* pAhi = smem + (buf - sb);
        char* pAlo = pAhi + 16384;
        #pragma unroll
        for (int i = 0; i < 4; ++i) {
            float4 f = areg[i];
            uint2 uh, ul;
            split2(f.x, f.y, uh.x, ul.x);
            split2(f.z, f.w, uh.y, ul.y);
            uint32_t off = sw128((uint32_t)(row * 128 + (cq + i * 4) * 2));
            *(uint2*)(pAhi + off) = uh;
            *(uint2*)(pAlo + off) = ul;
        }
    };
    auto loadW = [&](int c, uint32_t buf) {
        int kg = c * BK;
        const __nv_bfloat16* sh = g_Whi + (size_t)row * KTOT + kg + cq;
        const __nv_bfloat16* sl = g_Wlo + (size_t)row * KTOT + kg + cq;
        #pragma unroll
        for (int i = 0; i < 2; ++i) {
            uint32_t off = sw128((uint32_t)(row * 128 + (cq + i * 8) * 2));
            cp16(buf + 32768 + off, sh + i * 8);
            cp16(buf + 49152 + off, sl + i * 8);
        }
    };

    loadA(0); storeA(BASE + 0 * STAGE); loadW(0, BASE + 0 * STAGE); CP_COMMIT();
    loadA(1); storeA(BASE + 1 * STAGE); loadW(1, BASE + 1 * STAGE); CP_COMMIT();
    loadA(2);

    for (int c = 0; c < NCH; ++c) {
        if (c + 1 < NCH) CP_WAIT1(); else CP_WAIT0();
        __syncthreads();
        if (c + 2 < NCH) {
            uint32_t nbuf = BASE + (uint32_t)((c + 2) % 3) * STAGE;
            storeA(nbuf);
            loadW(c + 2, nbuf);
            CP_COMMIT();
            if (c + 3 < NCH) loadA(c + 3);
        }
        uint32_t cur = BASE + (uint32_t)(c % 3) * STAGE;
        compute_c16(cur, cur + 16384, cur + 32768, cur + 49152, fm, acc);
    }

    __syncthreads();
    float* Vs = (float*)(smem + 2048);
    const uint32_t CN = BASE + 1 * STAGE;
    const uint32_t WT = BASE + 2 * STAGE;

    const int schunk = (tid >> 1) & 1;
    const int sch = (tid & 1) * 32;
    auto loadWpair = [&](const __nv_bfloat16* hi, const __nv_bfloat16* lo, uint32_t dst) {
        const __nv_bfloat16* h = hi + (size_t)row * HID + schunk * BK + sch;
        const __nv_bfloat16* l = lo + (size_t)row * HID + schunk * BK + sch;
        #pragma unroll
        for (int i = 0; i < 4; ++i) {
            uint32_t off = sw128((uint32_t)(row * 128 + (sch + i * 8) * 2));
            cp16(dst + schunk * 32768 + off, h + i * 8);
            cp16(dst + schunk * 32768 + 16384 + off, l + i * 8);
        }
    };
    if (isQuery) { loadWpair(g_Wvhi, g_Wvlo, WT); CP_COMMIT(); }

    {
        const int g = lane >> 2, t = lane & 3;
        #pragma unroll
        for (int mt = 0; mt < 2; ++mt) {
            int r0 = mw * 32 + mt * 16 + g;
            #pragma unroll
            for (int j = 0; j < 4; ++j) {
                int col = nw * 32 + j * 8 + t * 2;
                float b0 = bsum[col], b1v = bsum[col + 1];
                *(float2*)&Vs[r0 * 128 + col] =
                    make_float2(acc[mt][j][0] + b0, acc[mt][j][1] + b1v);
                *(float2*)&Vs[(r0 + 8) * 128 + col] =
                    make_float2(acc[mt][j][2] + b0, acc[mt][j][3] + b1v);
            }
        }
    }
    __syncthreads();

    const int cch = lane >> 4;
    const int lc  = (lane * 4) & 63;
    {
        float4 gg = ((const float4*)g1)[lane];
        float4 bb = ((const float4*)b1)[lane];
        char* pNhi = smem + 2048 + STAGE + cch * 32768;
        char* pNlo = pNhi + 16384;
        for (int tt = wid * 8; tt < wid * 8 + 8; ++tt) {
            float4 x = ((const float4*)&Vs[tt * 128])[lane];
            float s = x.x + x.y + x.z + x.w;
            #pragma unroll
            for (int o = 16; o > 0; o >>= 1) s += __shfl_xor_sync(0xffffffffu, s, o);
            float mean = s * (1.0f / 128.0f);
            float d0 = x.x - mean, d1 = x.y - mean, d2 = x.z - mean, d3 = x.w - mean;
            float v = d0*d0 + d1*d1 + d2*d2 + d3*d3;
            #pragma unroll
            for (int o = 16; o > 0; o >>= 1) v += __shfl_xor_sync(0xffffffffu, v, o);
            float inv = rsqrtf(v * (1.0f / 128.0f) + 1e-5f);
            float y0 = d0 * inv * gg.x + bb.x;
            float y1 = d1 * inv * gg.y + bb.y;
            float y2 = d2 * inv * gg.z + bb.z;
            float y3 = d3 * inv * gg.w + bb.w;
            if (!isQuery) {
                float4 y = make_float4(y0, y1, y2, y3);
                ((float4*)&g_C[(size_t)(tokbase + tt) * HID])[lane] = y;
            } else {
                uint2 uh, ul;
                split2(y0, y1, uh.x, ul.x);
                split2(y2, y3, uh.y, ul.y);
                uint32_t off = sw128((uint32_t)(tt * 128 + lc * 2));
                *(uint2*)(pNhi + off) = uh;
                *(uint2*)(pNlo + off) = ul;
            }
        }
    }
    if (!isQuery) return;

    CP_WAIT0();
    __syncthreads();

    #pragma unroll
    for (int mt = 0; mt < 2; ++mt)
        #pragma unroll
        for (int j = 0; j < 4; ++j)
            #pragma unroll
            for (int q = 0; q < 4; ++q) acc[mt][j][q] = 0.0f;
    #pragma unroll
    for (int c = 0; c < 2; ++c)
        compute_c16(CN + c * 32768, CN + c * 32768 + 16384,
                    WT + c * 32768, WT + c * 32768 + 16384, fm, acc);
    __syncthreads();

    loadWpair(g_Wohi, g_Wolo, CN);
    CP_COMMIT();

    {
        const int g = lane >> 2, t = lane & 3;
        #pragma unroll
        for (int mt = 0; mt < 2; ++mt) {
            int r0 = mw * 32 + mt * 16 + g;
            #pragma unroll
            for (int j = 0; j < 4; ++j) {
                int col = nw * 32 + j * 8 + t * 2;
                float b0 = bv[col], b1v = bv[col + 1];
                *(float2*)&Vs[r0 * 128 + col] =
                    make_float2(acc[mt][j][0] + b0, acc[mt][j][1] + b1v);
                *(float2*)&Vs[(r0 + 8) * 128 + col] =
                    make_float2(acc[mt][j][2] + b0, acc[mt][j][3] + b1v);
            }
        }
    }
    __syncthreads();

    {
        float4 gg = ((const float4*)g2)[lane];
        float4 bb = ((const float4*)b2)[lane];
        char* pNhi = smem + 2048 + 2 * STAGE + cch * 32768;
        char* pNlo = pNhi + 16384;
        for (int tt = wid * 8; tt < wid * 8 + 8; ++tt) {
            float4 x = ((const float4*)&Vs[tt * 128])[lane];
            float s = x.x + x.y + x.z + x.w;
            #pragma unroll
            for (int o = 16; o > 0; o >>= 1) s += __shfl_xor_sync(0xffffffffu, s, o);
            float mean = s * (1.0f / 128.0f);
            float d0 = x.x - mean, d1 = x.y - mean, d2 = x.z - mean, d3 = x.w - mean;
            float v = d0*d0 + d1*d1 + d2*d2 + d3*d3;
            #pragma unroll
            for (int o = 16; o > 0; o >>= 1) v += __shfl_xor_sync(0xffffffffu, v, o);
            float inv = rsqrtf(v * (1.0f / 128.0f) + 1e-5f);
            float y0 = d0 * inv * gg.x + bb.x;
            float y1 = d1 * inv * gg.y + bb.y;
            float y2 = d2 * inv * gg.z + bb.z;
            float y3 = d3 * inv * gg.w + bb.w;
            uint2 uh, ul;
            split2(y0, y1, uh.x, ul.x);
            split2(y2, y3, uh.y, ul.y);
            uint32_t off = sw128((uint32_t)(tt * 128 + lc * 2));
            *(uint2*)(pNhi + off) = uh;
            *(uint2*)(pNlo + off) = ul;
        }
    }
    CP_WAIT0();
    __syncthreads();

    #pragma unroll
    for (int mt = 0; mt < 2; ++mt)
        #pragma unroll
        for (int j = 0; j < 4; ++j)
            #pragma unroll
            for (int q = 0; q < 4; ++q) acc[mt][j][q] = 0.0f;
    #pragma unroll
    for (int c = 0; c < 2; ++c)
        compute_c16(WT + c * 32768, WT + c * 32768 + 16384,
                    CN + c * 32768, CN + c * 32768 + 16384, fm, acc);

    {
        const int g = lane >> 2, t = lane & 3;
        const int qbase = tokbase - TSUP;
        #pragma unroll
        for (int mt = 0; mt < 2; ++mt) {
            int r0 = qbase + mw * 32 + mt * 16 + g;
            #pragma unroll
            for (int j = 0; j < 4; ++j) {
                int col = nw * 32 + j * 8 + t * 2;
                float b0 = bo[col], b1v = bo[col + 1];
                *(float2*)&g_QF[(size_t)r0 * HID + col] =
                    make_float2(acc[mt][j][0] + b0, acc[mt][j][1] + b1v);
                *(float2*)&g_QF[(size_t)(r0 + 8) * HID + col] =
                    make_float2(acc[mt][j][2] + b0, acc[mt][j][3] + b1v);
            }
        }
    }
}

// ---------------------------------------------------------------------------
// Fused tail v3 (round-13 memory pattern, 384 threads):
// groups 0/1/2 compute Q/K/V GEMVs CONCURRENTLY; rest of the phases use the
// round-13 structure with guards. One block per task.
// ---------------------------------------------------------------------------
__global__ void __launch_bounds__(384) k_tail(
    const float* __restrict__ C,
    const float* __restrict__ Wq, const float* __restrict__ bq,
    const float* __restrict__ Wk, const float* __restrict__ bk,
    const float* __restrict__ Wv, const float* __restrict__ bv,
    const float* __restrict__ g2, const float* __restrict__ b2,
    const float* __restrict__ Wo, const float* __restrict__ bo,
    const float* __restrict__ QF, float* __restrict__ out)
{
    __shared__ float cs[4][HID], qs[4][HID], ks_[4][HID], vs[4][HID];
    __shared__ float am[4][4];
    __shared__ float cx[4][HID];
    __shared__ float pn[4][HID];
    int t = blockIdx.x;
    int tid = threadIdx.x;
    int grp = tid >> 7;        // 0,1,2
    int j = tid & 127;
    const float* base = C + (size_t)t * 4 * HID;
    if (grp == 0) {
        #pragma unroll
        for (int s = 0; s < 4; ++s) cs[s][j] = base[s * HID + j];
    }
    __syncthreads();

    // QKV GEMVs in parallel across groups (round-13 per-thread row pattern,
    // L1-resident reuse)
    {
        const float* W  = (grp == 0) ? Wq : (grp == 1) ? Wk : Wv;
        const float* bb = (grp == 0) ? bq : (grp == 1) ? bk : bv;
        float a[4] = {0, 0, 0, 0};
        const float4* w4p = (const float4*)(W + (size_t)j * HID);
        #pragma unroll 4
        for (int d4 = 0; d4 < 32; ++d4) {
            float4 w4 = w4p[d4];
            #pragma unroll
            for (int s = 0; s < 4; ++s) {
                a[s] += w4.x * cs[s][d4*4+0] + w4.y * cs[s][d4*4+1]
                      + w4.z * cs[s][d4*4+2] + w4.w * cs[s][d4*4+3];
            }
        }
        float* dst = (grp == 0) ? &qs[0][0] : (grp == 1) ? &ks_[0][0] : &vs[0][0];
        #pragma unroll
        for (int s = 0; s < 4; ++s) dst[s * HID + j] = a[s] + bb[j];
    }
    __syncthreads();

    if (tid < 16) {
        int s = tid >> 2, s2 = tid & 3;
        float d = 0.0f;
        for (int dd = 0; dd < HID; ++dd) d += qs[s][dd] * ks_[s2][dd];
        am[s][s2] = d * (1.0f / (sqrtf(128.0f) + 1e-8f));
    }
    __syncthreads();
    if (tid < 4) {
        float r[4];
        float mx = -1e30f;
        #pragma unroll
        for (int c = 0; c < 4; ++c) { r[c] = am[tid][c]; mx = fmaxf(mx, r[c]); }
        float sum = 0.0f;
        #pragma unroll
        for (int c = 0; c < 4; ++c) { r[c] = expf(r[c] - mx); sum += r[c]; }
        #pragma unroll
        for (int c = 0; c < 4; ++c) r[c] /= sum;
        float sum2 = 0.0f;
        #pragma unroll
        for (int c = 0; c < 4; ++c) { r[c] += 1e-10f; sum2 += r[c]; }
        #pragma unroll
        for (int c = 0; c < 4; ++c) {
            r[c] /= sum2;
            am[tid][c] = fminf(fmaxf(r[c], 1e-7f), 1.0f);
        }
    }
    __syncthreads();
    if (grp == 0) {
        #pragma unroll
        for (int s = 0; s < 4; ++s) {
            float v = 0.0f;
            #pragma unroll
            for (int s2 = 0; s2 < 4; ++s2) v += am[s][s2] * vs[s2][j];
            cx[s][j] = v;
        }
    }
    __syncthreads();
    {
        int w = tid >> 5, lane = tid & 31;
        if (w < 4) {
            float x0 = cx[w][lane], x1 = cx[w][lane+32], x2 = cx[w][lane+64], x3 = cx[w][lane+96];
            float s = x0 + x1 + x2 + x3;
            #pragma unroll
            for (int o = 16; o > 0; o >>= 1) s += __shfl_xor_sync(0xffffffffu, s, o);
            float mean = s * (1.0f / 128.0f);
            float d0 = x0 - mean, d1 = x1 - mean, d2 = x2 - mean, d3 = x3 - mean;
            float v = d0*d0 + d1*d1 + d2*d2 + d3*d3;
            #pragma unroll
            for (int o = 16; o > 0; o >>= 1) v += __shfl_xor_sync(0xffffffffu, v, o);
            float inv = rsqrtf(v * (1.0f / 128.0f) + 1e-5f);
            cx[w][lane]    = d0 * inv * g2[lane]    + b2[lane];
            cx[w][lane+32] = d1 * inv * g2[lane+32] + b2[lane+32];
            cx[w][lane+64] = d2 * inv * g2[lane+64] + b2[lane+64];
            cx[w][lane+96] = d3 * inv * g2[lane+96] + b2[lane+96];
        }
    }
    __syncthreads();
    if (grp == 0) {
        const float4* wo = (const float4*)(Wo + (size_t)j * HID);
        float ao[4] = {0, 0, 0, 0};
        #pragma unroll 4
        for (int d4 = 0; d4 < 32; ++d4) {
            float4 w4 = wo[d4];
            #pragma unroll
            for (int s = 0; s < 4; ++s) {
                ao[s] += w4.x * cx[s][d4*4+0] + w4.y * cx[s][d4*4+1]
                       + w4.z * cx[s][d4*4+2] + w4.w * cx[s][d4*4+3];
            }
        }
        #pragma unroll
        for (int s = 0; s < 4; ++s)
            qs[s][j] = ao[s] + bo[j];     // SF rows (reuse qs)
    }
    __syncthreads();

    // normalize SF rows -> pn (first 4 warps)
    int w = tid >> 5, lane = tid & 31;
    if (w < 4) {
        float4 x = ((const float4*)qs[w])[lane];
        float n2 = x.x*x.x + x.y*x.y + x.z*x.z + x.w*x.w;
        #pragma unroll
        for (int o = 16; o > 0; o >>= 1) n2 += __shfl_xor_sync(0xffffffffu, n2, o);
        float inv = 1.0f / fmaxf(sqrtf(n2), 1e-8f);
        float4 y;
        y.x = x.x * inv; y.y = x.y * inv; y.z = x.z * inv; y.w = x.w * inv;
        ((float4*)pn[w])[lane] = y;
    }
    __syncthreads();

    // cosine logits against this task's 64 QF rows, spread over 12 warps
    for (int q = w; q < 64; q += 12) {
        const float4* row = (const float4*)(QF + (size_t)(t*64 + q) * HID);
        float4 x = row[lane];
        float n2 = x.x*x.x + x.y*x.y + x.z*x.z + x.w*x.w;
        float d[4];
        #pragma unroll
        for (int c = 0; c < 4; ++c) {
            float4 p = ((const float4*)pn[c])[lane];
            d[c] = x.x*p.x + x.y*p.y + x.z*p.z + x.w*p.w;
        }
        #pragma unroll
        for (int o = 16; o > 0; o >>= 1) {
            n2 += __shfl_xor_sync(0xffffffffu, n2, o);
            #pragma unroll
            for (int c = 0; c < 4; ++c)
                d[c] += __shfl_xor_sync(0xffffffffu, d[c], o);
        }
        if (lane == 0) {
            float inv = 10.0f / fmaxf(sqrtf(n2), 1e-8f);
            float4 r;
            r.x = d[0]*inv; r.y = d[1]*inv; r.z = d[2]*inv; r.w = d[3]*inv;
            ((float4*)(out + ((size_t)t*64 + q) * 4))[0] = r;
        }
    }
}

extern "C" void kernel_launch(void* const* d_in, const int* in_sizes, int n_in,
                              void* d_out, int out_size)
{
    const float* s_img = (const float*)d_in[0];
    const float* s_txt = (const float*)d_in[1];
    /* d_in[2] = support_labels (unused) */
    const float* q_img = (const float*)d_in[3];
    const float* q_txt = (const float*)d_in[4];
    const float* Wi = (const float*)d_in[5];
    const float* bi = (const float*)d_in[6];
    const float* Wt = (const float*)d_in[7];
    const float* bt = (const float*)d_in[8];
    const float* g1 = (const float*)d_in[9];
    const float* b1 = (const float*)d_in[10];
    const float* Wq = (const float*)d_in[11];
    const float* bq = (const float*)d_in[12];
    const float* Wk = (const float*)d_in[13];
    const float* bk = (const float*)d_in[14];
    const float* Wv = (const float*)d_in[15];
    const float* bv = (const float*)d_in[16];
    const float* g2 = (const float*)d_in[17];
    const float* b2 = (const float*)d_in[18];
    const float* Wo = (const float*)d_in[19];
    const float* bo = (const float*)d_in[20];

    float *pC, *pQF;
    cudaGetSymbolAddress((void**)&pC, g_C);
    cudaGetSymbolAddress((void**)&pQF, g_QF);

    const int SMEM_IN = 2048 + 3 * STAGE;        // 198656
    static bool attr_set = false;
    if (!attr_set) {
        cudaFuncSetAttribute(k_input_mega,
                             cudaFuncAttributeMaxDynamicSharedMemorySize, SMEM_IN);
        attr_set = true;
    }

    // 1) single weight-preconvert launch
    k_wconv_all<<<384, 256>>>(Wi, Wt, Wv, Wo);
    // 2) mega kernel: input projection + LN1 (+ full query chain for query blocks)
    k_input_mega<<<NTOK / 128, 512, SMEM_IN>>>(s_img, s_txt, q_img, q_txt,
                                               bi, bt, g1, b1, bv, g2, b2, bo);
    // 3) fused tail: support attention + cosine logits, one block per task
    k_tail<<<256, 384>>>(pC, Wq, bq, Wk, bk, Wv, bv, g2, b2, Wo, bo,
                         pQF, (float*)d_out);
}

// round 17
// speedup vs baseline: 1.5886x; 1.0292x over previous
#include <cuda_runtime.h>
#include <cuda_bf16.h>
#include <math.h>
#include <stdint.h>

#define HID 128
#define DI 2048
#define DT 768
#define KTOT 2816
#define TSUP 1024
#define TQRY 16384
#define NTOK 17408
#define BK 64
#define NCH 44   /* 2816 / 64 */
#define STAGE 65536   /* per-stage: Ahi 16K, Alo 16K, Whi 16K, Wlo 16K */

// Scratch (static __device__ per allocation rules)
__device__ float g_C[NTOK * HID];     // LN1'd features (support blocks only)
__device__ float g_QF[TQRY * HID];
__device__ __nv_bfloat16 g_Whi[HID * KTOT];
__device__ __nv_bfloat16 g_Wlo[HID * KTOT];
__device__ __nv_bfloat16 g_Wvhi[HID * HID];
__device__ __nv_bfloat16 g_Wvlo[HID * HID];
__device__ __nv_bfloat16 g_Wohi[HID * HID];
__device__ __nv_bfloat16 g_Wolo[HID * HID];

// ---------------------------------------------------------------------------
// helpers
// ---------------------------------------------------------------------------
__device__ __forceinline__ uint32_t smem_u32_of(const void* p) {
    uint32_t a;
    asm("{ .reg .u64 t; cvta.to.shared.u64 t, %1; cvt.u32.u64 %0, t; }"
        : "=r"(a) : "l"(p));
    return a;
}
static __device__ __forceinline__ uint32_t sw128(uint32_t off) {
    return off ^ ((off >> 3) & 0x70);
}
__device__ __forceinline__ void ldsm4(uint32_t* r, uint32_t addr) {
    asm volatile("ldmatrix.sync.aligned.m8n8.x4.shared.b16 {%0,%1,%2,%3}, [%4];"
                 : "=r"(r[0]), "=r"(r[1]), "=r"(r[2]), "=r"(r[3]) : "r"(addr));
}
__device__ __forceinline__ void mma16816(float* c, const uint32_t* a, const uint32_t* b) {
    asm volatile(
        "mma.sync.aligned.m16n8k16.row.col.f32.bf16.bf16.f32 "
        "{%0,%1,%2,%3}, {%4,%5,%6,%7}, {%8,%9}, {%0,%1,%2,%3};"
        : "+f"(c[0]), "+f"(c[1]), "+f"(c[2]), "+f"(c[3])
        : "r"(a[0]), "r"(a[1]), "r"(a[2]), "r"(a[3]), "r"(b[0]), "r"(b[1]));
}
__device__ __forceinline__ void cp16(uint32_t dst, const void* src) {
    asm volatile("cp.async.cg.shared.global [%0], [%1], 16;"
                 :: "r"(dst), "l"(src) : "memory");
}
#define CP_COMMIT() asm volatile("cp.async.commit_group;" ::: "memory")
#define CP_WAIT0()  asm volatile("cp.async.wait_group 0;" ::: "memory")
#define CP_WAIT1()  asm volatile("cp.async.wait_group 1;" ::: "memory")

__device__ __forceinline__ void split2(float x, float y, uint32_t& hi, uint32_t& lo) {
    __nv_bfloat162 h = __float22bfloat162_rn(make_float2(x, y));
    float2 hf = __bfloat1622float2(h);
    __nv_bfloat162 l = __float22bfloat162_rn(make_float2(x - hf.x, y - hf.y));
    hi = *(uint32_t*)&h;
    lo = *(uint32_t*)&l;
}

// ---------------------------------------------------------------------------
// 16-warp fragment map + 32x32-tile bf16x3 compute over one 64-K chunk
// ---------------------------------------------------------------------------
struct Frag16 {
    uint32_t abase[2], aswz[2], bbase[2], bswz[2];
};
__device__ __forceinline__ void make_frag16(Frag16& fm, int lane, int mw, int nw) {
    #pragma unroll
    for (int mt = 0; mt < 2; ++mt) {
        uint32_t rb = (uint32_t)(mw * 32 + mt * 16 + (lane & 15)) * 128 + (lane >> 4) * 16;
        fm.abase[mt] = rb; fm.aswz[mt] = (rb >> 3) & 0x70;
    }
    #pragma unroll
    for (int p = 0; p < 2; ++p) {
        uint32_t rb = (uint32_t)(nw * 32 + p * 16 + ((lane >> 4) & 1) * 8 + (lane & 7)) * 128
                    + ((lane >> 3) & 1) * 16;
        fm.bbase[p] = rb; fm.bswz[p] = (rb >> 3) & 0x70;
    }
}
__device__ __forceinline__ void compute_c16(
    uint32_t AHI, uint32_t ALO, uint32_t WHI, uint32_t WLO,
    const Frag16& fm, float (*acc)[4][4])
{
    #pragma unroll
    for (int ks = 0; ks < 4; ++ks) {
        uint32_t ahi[2][4], alo[2][4];
        #pragma unroll
        for (int mt = 0; mt < 2; ++mt) {
            uint32_t o = (fm.abase[mt] + ks * 32) ^ fm.aswz[mt];
            ldsm4(ahi[mt], AHI + o);
            ldsm4(alo[mt], ALO + o);
        }
        uint32_t bhi[2][4], blo[2][4];
        #pragma unroll
        for (int p = 0; p < 2; ++p) {
            uint32_t o = (fm.bbase[p] + ks * 32) ^ fm.bswz[p];
            ldsm4(bhi[p], WHI + o);
            ldsm4(blo[p], WLO + o);
        }
        #pragma unroll
        for (int mt = 0; mt < 2; ++mt)
            #pragma unroll
            for (int j = 0; j < 4; ++j)
                mma16816(acc[mt][j], ahi[mt], &bhi[j >> 1][(j & 1) * 2]);
        #pragma unroll
        for (int mt = 0; mt < 2; ++mt)
            #pragma unroll
            for (int j = 0; j < 4; ++j)
                mma16816(acc[mt][j], ahi[mt], &blo[j >> 1][(j & 1) * 2]);
        #pragma unroll
        for (int mt = 0; mt < 2; ++mt)
            #pragma unroll
            for (int j = 0; j < 4; ++j)
                mma16816(acc[mt][j], alo[mt], &bhi[j >> 1][(j & 1) * 2]);
    }
}

// ---------------------------------------------------------------------------
// Single weight-preconvert kernel: blocks [0,352) main W, [352,368) Wv,
// [368,384) Wo.
// ---------------------------------------------------------------------------
__global__ void __launch_bounds__(256) k_wconv_all(
    const float* __restrict__ Wi, const float* __restrict__ Wt,
    const float* __restrict__ Wv, const float* __restrict__ Wo)
{
    int b = blockIdx.x;
    if (b < 352) {
        int f4 = b * 256 + threadIdx.x;
        if (f4 >= HID * KTOT / 4) return;
        int row = f4 / (KTOT / 4);
        int col = (f4 % (KTOT / 4)) * 4;
        float4 v;
        if (col < DI) v = *(const float4*)(Wi + (size_t)row * DI + col);
        else          v = *(const float4*)(Wt + (size_t)row * DT + (col - DI));
        uint2 uh, ul;
        split2(v.x, v.y, uh.x, ul.x);
        split2(v.z, v.w, uh.y, ul.y);
        *(uint2*)(g_Whi + (size_t)row * KTOT + col) = uh;
        *(uint2*)(g_Wlo + (size_t)row * KTOT + col) = ul;
    } else {
        const bool isV = (b < 368);
        int f4 = (b - (isV ? 352 : 368)) * 256 + threadIdx.x;
        const float* W = isV ? Wv : Wo;
        __nv_bfloat16* hi = isV ? g_Wvhi : g_Wohi;
        __nv_bfloat16* lo = isV ? g_Wvlo : g_Wolo;
        float4 v = *(const float4*)(W + (size_t)f4 * 4);
        uint2 uh, ul;
        split2(v.x, v.y, uh.x, ul.x);
        split2(v.z, v.w, uh.y, ul.y);
        *(uint2*)(hi + (size_t)f4 * 4) = uh;
        *(uint2*)(lo + (size_t)f4 * 4) = ul;
    }
}

// ---------------------------------------------------------------------------
// MEGA KERNEL (unchanged): input projection + LN1; query blocks continue
// through LN2/Wv/Wo to g_QF, support blocks write g_C.
// ---------------------------------------------------------------------------
__global__ void __launch_bounds__(512) k_input_mega(
    const float* __restrict__ s_img, const float* __restrict__ s_txt,
    const float* __restrict__ q_img, const float* __restrict__ q_txt,
    const float* __restrict__ bi, const float* __restrict__ bt,
    const float* __restrict__ g1, const float* __restrict__ b1,
    const float* __restrict__ bv, const float* __restrict__ g2,
    const float* __restrict__ b2, const float* __restrict__ bo)
{
    extern __shared__ char smem[];
    const uint32_t sb = smem_u32_of(smem);
    float* bsum = (float*)smem;
    const uint32_t BASE = sb + 2048;

    const int tid = threadIdx.x, lane = tid & 31, wid = tid >> 5;
    const int mw = wid & 3, nw = wid >> 2;
    const int tokbase = blockIdx.x * 128;
    const bool isQuery = (tokbase >= TSUP);

    const float* img; const float* txt;
    if (!isQuery) {
        img = s_img + (size_t)tokbase * DI;
        txt = s_txt + (size_t)tokbase * DT;
    } else {
        img = q_img + (size_t)(tokbase - TSUP) * DI;
        txt = q_txt + (size_t)(tokbase - TSUP) * DT;
    }
    if (tid < HID) bsum[tid] = bi[tid] + bt[tid];

    const int row = tid >> 2;
    const int cq  = (tid & 3) * 16;

    Frag16 fm;
    make_frag16(fm, lane, mw, nw);

    float acc[2][4][4];
    #pragma unroll
    for (int mt = 0; mt < 2; ++mt)
        #pragma unroll
        for (int j = 0; j < 4; ++j)
            #pragma unroll
            for (int q = 0; q < 4; ++q) acc[mt][j][q] = 0.0f;

    float4 areg[4];
    auto loadA = [&](int c) {
        int kg = c * BK;
        const float4* ap;
        if (kg < DI) ap = (const float4*)(img + (size_t)row * DI + kg + cq);
        else         ap = (const float4*)(txt + (size_t)row * DT + (kg - DI) + cq);
        #pragma unroll
        for (int i = 0; i < 4; ++i) areg[i] = ap[i];
    };
    auto storeA = [&](uint32_t buf) {
        char* pAhi = smem + (buf - sb);
        char* pAlo = pAhi + 16384;
        #pragma unroll
        for (int i = 0; i < 4; ++i) {
            float4 f = areg[i];
            uint2 uh, ul;
            split2(f.x, f.y, uh.x, ul.x);
            split2(f.z, f.w, uh.y, ul.y);
            uint32_t off = sw128((uint32_t)(row * 128 + (cq + i * 4) * 2));
            *(uint2*)(pAhi + off) = uh;
            *(uint2*)(pAlo + off) = ul;
        }
    };
    auto loadW = [&](int c, uint32_t buf) {
        int kg = c * BK;
        const __nv_bfloat16* sh = g_Whi + (size_t)row * KTOT + kg + cq;
        const __nv_bfloat16* sl = g_Wlo + (size_t)row * KTOT + kg + cq;
        #pragma unroll
        for (int i = 0; i < 2; ++i) {
            uint32_t off = sw128((uint32_t)(row * 128 + (cq + i * 8) * 2));
            cp16(buf + 32768 + off, sh + i * 8);
            cp16(buf + 49152 + off, sl + i * 8);
        }
    };

    loadA(0); storeA(BASE + 0 * STAGE); loadW(0, BASE + 0 * STAGE); CP_COMMIT();
    loadA(1); storeA(BASE + 1 * STAGE); loadW(1, BASE + 1 * STAGE); CP_COMMIT();
    loadA(2);

    for (int c = 0; c < NCH; ++c) {
        if (c + 1 < NCH) CP_WAIT1(); else CP_WAIT0();
        __syncthreads();
        if (c + 2 < NCH) {
            uint32_t nbuf = BASE + (uint32_t)((c + 2) % 3) * STAGE;
            storeA(nbuf);
            loadW(c + 2, nbuf);
            CP_COMMIT();
            if (c + 3 < NCH) loadA(c + 3);
        }
        uint32_t cur = BASE + (uint32_t)(c % 3) * STAGE;
        compute_c16(cur, cur + 16384, cur + 32768, cur + 49152, fm, acc);
    }

    __syncthreads();
    float* Vs = (float*)(smem + 2048);
    const uint32_t CN = BASE + 1 * STAGE;
    const uint32_t WT = BASE + 2 * STAGE;

    const int schunk = (tid >> 1) & 1;
    const int sch = (tid & 1) * 32;
    auto loadWpair = [&](const __nv_bfloat16* hi, const __nv_bfloat16* lo, uint32_t dst) {
        const __nv_bfloat16* h = hi + (size_t)row * HID + schunk * BK + sch;
        const __nv_bfloat16* l = lo + (size_t)row * HID + schunk * BK + sch;
        #pragma unroll
        for (int i = 0; i < 4; ++i) {
            uint32_t off = sw128((uint32_t)(row * 128 + (sch + i * 8) * 2));
            cp16(dst + schunk * 32768 + off, h + i * 8);
            cp16(dst + schunk * 32768 + 16384 + off, l + i * 8);
        }
    };
    if (isQuery) { loadWpair(g_Wvhi, g_Wvlo, WT); CP_COMMIT(); }

    {
        const int g = lane >> 2, t = lane & 3;
        #pragma unroll
        for (int mt = 0; mt < 2; ++mt) {
            int r0 = mw * 32 + mt * 16 + g;
            #pragma unroll
            for (int j = 0; j < 4; ++j) {
                int col = nw * 32 + j * 8 + t * 2;
                float b0 = bsum[col], b1v = bsum[col + 1];
                *(float2*)&Vs[r0 * 128 + col] =
                    make_float2(acc[mt][j][0] + b0, acc[mt][j][1] + b1v);
                *(float2*)&Vs[(r0 + 8) * 128 + col] =
                    make_float2(acc[mt][j][2] + b0, acc[mt][j][3] + b1v);
            }
        }
    }
    __syncthreads();

    const int cch = lane >> 4;
    const int lc  = (lane * 4) & 63;
    {
        float4 gg = ((const float4*)g1)[lane];
        float4 bb = ((const float4*)b1)[lane];
        char* pNhi = smem + 2048 + STAGE + cch * 32768;
        char* pNlo = pNhi + 16384;
        for (int tt = wid * 8; tt < wid * 8 + 8; ++tt) {
            float4 x = ((const float4*)&Vs[tt * 128])[lane];
            float s = x.x + x.y + x.z + x.w;
            #pragma unroll
            for (int o = 16; o > 0; o >>= 1) s += __shfl_xor_sync(0xffffffffu, s, o);
            float mean = s * (1.0f / 128.0f);
            float d0 = x.x - mean, d1 = x.y - mean, d2 = x.z - mean, d3 = x.w - mean;
            float v = d0*d0 + d1*d1 + d2*d2 + d3*d3;
            #pragma unroll
            for (int o = 16; o > 0; o >>= 1) v += __shfl_xor_sync(0xffffffffu, v, o);
            float inv = rsqrtf(v * (1.0f / 128.0f) + 1e-5f);
            float y0 = d0 * inv * gg.x + bb.x;
            float y1 = d1 * inv * gg.y + bb.y;
            float y2 = d2 * inv * gg.z + bb.z;
            float y3 = d3 * inv * gg.w + bb.w;
            if (!isQuery) {
                float4 y = make_float4(y0, y1, y2, y3);
                ((float4*)&g_C[(size_t)(tokbase + tt) * HID])[lane] = y;
            } else {
                uint2 uh, ul;
                split2(y0, y1, uh.x, ul.x);
                split2(y2, y3, uh.y, ul.y);
                uint32_t off = sw128((uint32_t)(tt * 128 + lc * 2));
                *(uint2*)(pNhi + off) = uh;
                *(uint2*)(pNlo + off) = ul;
            }
        }
    }
    if (!isQuery) return;

    CP_WAIT0();
    __syncthreads();

    #pragma unroll
    for (int mt = 0; mt < 2; ++mt)
        #pragma unroll
        for (int j = 0; j < 4; ++j)
            #pragma unroll
            for (int q = 0; q < 4; ++q) acc[mt][j][q] = 0.0f;
    #pragma unroll
    for (int c = 0; c < 2; ++c)
        compute_c16(CN + c * 32768, CN + c * 32768 + 16384,
                    WT + c * 32768, WT + c * 32768 + 16384, fm, acc);
    __syncthreads();

    loadWpair(g_Wohi, g_Wolo, CN);
    CP_COMMIT();

    {
        const int g = lane >> 2, t = lane & 3;
        #pragma unroll
        for (int mt = 0; mt < 2; ++mt) {
            int r0 = mw * 32 + mt * 16 + g;
            #pragma unroll
            for (int j = 0; j < 4; ++j) {
                int col = nw * 32 + j * 8 + t * 2;
                float b0 = bv[col], b1v = bv[col + 1];
                *(float2*)&Vs[r0 * 128 + col] =
                    make_float2(acc[mt][j][0] + b0, acc[mt][j][1] + b1v);
                *(float2*)&Vs[(r0 + 8) * 128 + col] =
                    make_float2(acc[mt][j][2] + b0, acc[mt][j][3] + b1v);
            }
        }
    }
    __syncthreads();

    {
        float4 gg = ((const float4*)g2)[lane];
        float4 bb = ((const float4*)b2)[lane];
        char* pNhi = smem + 2048 + 2 * STAGE + cch * 32768;
        char* pNlo = pNhi + 16384;
        for (int tt = wid * 8; tt < wid * 8 + 8; ++tt) {
            float4 x = ((const float4*)&Vs[tt * 128])[lane];
            float s = x.x + x.y + x.z + x.w;
            #pragma unroll
            for (int o = 16; o > 0; o >>= 1) s += __shfl_xor_sync(0xffffffffu, s, o);
            float mean = s * (1.0f / 128.0f);
            float d0 = x.x - mean, d1 = x.y - mean, d2 = x.z - mean, d3 = x.w - mean;
            float v = d0*d0 + d1*d1 + d2*d2 + d3*d3;
            #pragma unroll
            for (int o = 16; o > 0; o >>= 1) v += __shfl_xor_sync(0xffffffffu, v, o);
            float inv = rsqrtf(v * (1.0f / 128.0f) + 1e-5f);
            float y0 = d0 * inv * gg.x + bb.x;
            float y1 = d1 * inv * gg.y + bb.y;
            float y2 = d2 * inv * gg.z + bb.z;
            float y3 = d3 * inv * gg.w + bb.w;
            uint2 uh, ul;
            split2(y0, y1, uh.x, ul.x);
            split2(y2, y3, uh.y, ul.y);
            uint32_t off = sw128((uint32_t)(tt * 128 + lc * 2));
            *(uint2*)(pNhi + off) = uh;
            *(uint2*)(pNlo + off) = ul;
        }
    }
    CP_WAIT0();
    __syncthreads();

    #pragma unroll
    for (int mt = 0; mt < 2; ++mt)
        #pragma unroll
        for (int j = 0; j < 4; ++j)
            #pragma unroll
            for (int q = 0; q < 4; ++q) acc[mt][j][q] = 0.0f;
    #pragma unroll
    for (int c = 0; c < 2; ++c)
        compute_c16(WT + c * 32768, WT + c * 32768 + 16384,
                    CN + c * 32768, CN + c * 32768 + 16384, fm, acc);

    {
        const int g = lane >> 2, t = lane & 3;
        const int qbase = tokbase - TSUP;
        #pragma unroll
        for (int mt = 0; mt < 2; ++mt) {
            int r0 = qbase + mw * 32 + mt * 16 + g;
            #pragma unroll
            for (int j = 0; j < 4; ++j) {
                int col = nw * 32 + j * 8 + t * 2;
                float b0 = bo[col], b1v = bo[col + 1];
                *(float2*)&g_QF[(size_t)r0 * HID + col] =
                    make_float2(acc[mt][j][0] + b0, acc[mt][j][1] + b1v);
                *(float2*)&g_QF[(size_t)(r0 + 8) * HID + col] =
                    make_float2(acc[mt][j][2] + b0, acc[mt][j][3] + b1v);
            }
        }
    }
}

// ---------------------------------------------------------------------------
// Fused tail (round-13 structure, proven): per task t — support attention
// (4 tokens) + cosine logits. One 128-thread block per task. Weights read
// via per-thread row LDG (L1-resident, serial one matrix at a time).
// Only change vs round-13: GEMV unroll 4 -> 8 for deeper MLP.
// ---------------------------------------------------------------------------
__global__ void __launch_bounds__(128) k_tail(
    const float* __restrict__ C,
    const float* __restrict__ Wq, const float* __restrict__ bq,
    const float* __restrict__ Wk, const float* __restrict__ bk,
    const float* __restrict__ Wv, const float* __restrict__ bv,
    const float* __restrict__ g2, const float* __restrict__ b2,
    const float* __restrict__ Wo, const float* __restrict__ bo,
    const float* __restrict__ QF, float* __restrict__ out)
{
    __shared__ float cs[4][HID], qs[4][HID], ks_[4][HID], vs[4][HID];
    __shared__ float am[4][4];
    __shared__ float cx[4][HID];
    __shared__ float pn[4][HID];
    int t = blockIdx.x;
    int j = threadIdx.x;
    const float* base = C + (size_t)t * 4 * HID;
    #pragma unroll
    for (int s = 0; s < 4; ++s) cs[s][j] = base[s * HID + j];
    __syncthreads();
    {
        float aq[4] = {0,0,0,0}, ak[4] = {0,0,0,0}, av[4] = {0,0,0,0};
        const float4* wq = (const float4*)(Wq + (size_t)j * HID);
        const float4* wk = (const float4*)(Wk + (size_t)j * HID);
        const float4* wv = (const float4*)(Wv + (size_t)j * HID);
        #pragma unroll 8
        for (int d4 = 0; d4 < 32; ++d4) {
            float4 q4 = wq[d4], k4 = wk[d4], v4 = wv[d4];
            #pragma unroll
            for (int s = 0; s < 4; ++s) {
                float c0 = cs[s][d4*4+0], c1 = cs[s][d4*4+1];
                float c2 = cs[s][d4*4+2], c3 = cs[s][d4*4+3];
                aq[s] += q4.x*c0 + q4.y*c1 + q4.z*c2 + q4.w*c3;
                ak[s] += k4.x*c0 + k4.y*c1 + k4.z*c2 + k4.w*c3;
                av[s] += v4.x*c0 + v4.y*c1 + v4.z*c2 + v4.w*c3;
            }
        }
        #pragma unroll
        for (int s = 0; s < 4; ++s) {
            qs[s][j]  = aq[s] + bq[j];
            ks_[s][j] = ak[s] + bk[j];
            vs[s][j]  = av[s] + bv[j];
        }
    }
    __syncthreads();
    if (j < 16) {
        int s = j >> 2, s2 = j & 3;
        float d = 0.0f;
        for (int dd = 0; dd < HID; ++dd) d += qs[s][dd] * ks_[s2][dd];
        am[s][s2] = d * (1.0f / (sqrtf(128.0f) + 1e-8f));
    }
    __syncthreads();
    if (j < 4) {
        float r[4];
        float mx = -1e30f;
        #pragma unroll
        for (int c = 0; c < 4; ++c) { r[c] = am[j][c]; mx = fmaxf(mx, r[c]); }
        float sum = 0.0f;
        #pragma unroll
        for (int c = 0; c < 4; ++c) { r[c] = expf(r[c] - mx); sum += r[c]; }
        #pragma unroll
        for (int c = 0; c < 4; ++c) r[c] /= sum;
        float sum2 = 0.0f;
        #pragma unroll
        for (int c = 0; c < 4; ++c) { r[c] += 1e-10f; sum2 += r[c]; }
        #pragma unroll
        for (int c = 0; c < 4; ++c) {
            r[c] /= sum2;
            am[j][c] = fminf(fmaxf(r[c], 1e-7f), 1.0f);
        }
    }
    __syncthreads();
    #pragma unroll
    for (int s = 0; s < 4; ++s) {
        float v = 0.0f;
        #pragma unroll
        for (int s2 = 0; s2 < 4; ++s2) v += am[s][s2] * vs[s2][j];
        cx[s][j] = v;
    }
    __syncthreads();
    {
        int w = j >> 5, lane = j & 31;
        float x0 = cx[w][lane], x1 = cx[w][lane+32], x2 = cx[w][lane+64], x3 = cx[w][lane+96];
        float s = x0 + x1 + x2 + x3;
        #pragma unroll
        for (int o = 16; o > 0; o >>= 1) s += __shfl_xor_sync(0xffffffffu, s, o);
        float mean = s * (1.0f / 128.0f);
        float d0 = x0 - mean, d1 = x1 - mean, d2 = x2 - mean, d3 = x3 - mean;
        float v = d0*d0 + d1*d1 + d2*d2 + d3*d3;
        #pragma unroll
        for (int o = 16; o > 0; o >>= 1) v += __shfl_xor_sync(0xffffffffu, v, o);
        float inv = rsqrtf(v * (1.0f / 128.0f) + 1e-5f);
        cx[w][lane]    = d0 * inv * g2[lane]    + b2[lane];
        cx[w][lane+32] = d1 * inv * g2[lane+32] + b2[lane+32];
        cx[w][lane+64] = d2 * inv * g2[lane+64] + b2[lane+64];
        cx[w][lane+96] = d3 * inv * g2[lane+96] + b2[lane+96];
    }
    __syncthreads();
    {
        const float4* wo = (const float4*)(Wo + (size_t)j * HID);
        float ao[4] = {0,0,0,0};
        #pragma unroll 8
        for (int d4 = 0; d4 < 32; ++d4) {
            float4 w4 = wo[d4];
            #pragma unroll
            for (int s = 0; s < 4; ++s) {
                ao[s] += w4.x * cx[s][d4*4+0] + w4.y * cx[s][d4*4+1]
                       + w4.z * cx[s][d4*4+2] + w4.w * cx[s][d4*4+3];
            }
        }
        #pragma unroll
        for (int s = 0; s < 4; ++s)
            qs[s][j] = ao[s] + bo[j];   // SF rows (reuse qs)
    }
    __syncthreads();

    // normalize SF rows -> pn
    int w = j >> 5, lane = j & 31;
    {
        float4 x = ((const float4*)qs[w])[lane];
        float n2 = x.x*x.x + x.y*x.y + x.z*x.z + x.w*x.w;
        #pragma unroll
        for (int o = 16; o > 0; o >>= 1) n2 += __shfl_xor_sync(0xffffffffu, n2, o);
        float inv = 1.0f / fmaxf(sqrtf(n2), 1e-8f);
        float4 y;
        y.x = x.x * inv; y.y = x.y * inv; y.z = x.z * inv; y.w = x.w * inv;
        ((float4*)pn[w])[lane] = y;
    }
    __syncthreads();

    // cosine logits against this task's 64 QF rows
    for (int q = w; q < 64; q += 4) {
        const float4* row = (const float4*)(QF + (size_t)(t*64 + q) * HID);
        float4 x = row[lane];
        float n2 = x.x*x.x + x.y*x.y + x.z*x.z + x.w*x.w;
        float d[4];
        #pragma unroll
        for (int c = 0; c < 4; ++c) {
            float4 p = ((const float4*)pn[c])[lane];
            d[c] = x.x*p.x + x.y*p.y + x.z*p.z + x.w*p.w;
        }
        #pragma unroll
        for (int o = 16; o > 0; o >>= 1) {
            n2 += __shfl_xor_sync(0xffffffffu, n2, o);
            #pragma unroll
            for (int c = 0; c < 4; ++c)
                d[c] += __shfl_xor_sync(0xffffffffu, d[c], o);
        }
        if (lane == 0) {
            float inv = 10.0f / fmaxf(sqrtf(n2), 1e-8f);
            float4 r;
            r.x = d[0]*inv; r.y = d[1]*inv; r.z = d[2]*inv; r.w = d[3]*inv;
            ((float4*)(out + ((size_t)t*64 + q) * 4))[0] = r;
        }
    }
}

extern "C" void kernel_launch(void* const* d_in, const int* in_sizes, int n_in,
                              void* d_out, int out_size)
{
    const float* s_img = (const float*)d_in[0];
    const float* s_txt = (const float*)d_in[1];
    /* d_in[2] = support_labels (unused) */
    const float* q_img = (const float*)d_in[3];
    const float* q_txt = (const float*)d_in[4];
    const float* Wi = (const float*)d_in[5];
    const float* bi = (const float*)d_in[6];
    const float* Wt = (const float*)d_in[7];
    const float* bt = (const float*)d_in[8];
    const float* g1 = (const float*)d_in[9];
    const float* b1 = (const float*)d_in[10];
    const float* Wq = (const float*)d_in[11];
    const float* bq = (const float*)d_in[12];
    const float* Wk = (const float*)d_in[13];
    const float* bk = (const float*)d_in[14];
    const float* Wv = (const float*)d_in[15];
    const float* bv = (const float*)d_in[16];
    const float* g2 = (const float*)d_in[17];
    const float* b2 = (const float*)d_in[18];
    const float* Wo = (const float*)d_in[19];
    const float* bo = (const float*)d_in[20];

    float *pC, *pQF;
    cudaGetSymbolAddress((void**)&pC, g_C);
    cudaGetSymbolAddress((void**)&pQF, g_QF);

    const int SMEM_IN = 2048 + 3 * STAGE;        // 198656
    static bool attr_set = false;
    if (!attr_set) {
        cudaFuncSetAttribute(k_input_mega,
                             cudaFuncAttributeMaxDynamicSharedMemorySize, SMEM_IN);
        attr_set = true;
    }

    // 1) single weight-preconvert launch
    k_wconv_all<<<384, 256>>>(Wi, Wt, Wv, Wo);
    // 2) mega kernel: input projection + LN1 (+ full query chain for query blocks)
    k_input_mega<<<NTOK / 128, 512, SMEM_IN>>>(s_img, s_txt, q_img, q_txt,
                                               bi, bt, g1, b1, bv, g2, b2, bo);
    // 3) fused tail: support attention + cosine logits, one block per task
    k_tail<<<256, 128>>>(pC, Wq, bq, Wk, bk, Wv, bv, g2, b2, Wo, bo,
                         pQF, (float*)d_out);
}